// round 3
// baseline (speedup 1.0000x reference)
#include <cuda_runtime.h>

// ---------------------------------------------------------------------------
// FAENet forward, fp32. Shapes: N=50000 nodes, E=800000 edges, H=256, F=128,
// G=50, TH=32, L=3, 32 graphs.
// ---------------------------------------------------------------------------

#define MAX_N 50000
#define MAX_E 800000

// Scratch (device globals; no runtime allocation allowed)
__device__ float g_h0 [MAX_N * 256];
__device__ float g_hb [MAX_N * 256];
__device__ float g_h  [MAX_N * 256];
__device__ float g_hd [MAX_N * 128];
__device__ float g_agg[MAX_N * 128];
__device__ float g_stats[512];          // [0:128) sum, [128:256) sumsq, [256:384) mean*ms, [384:512) scale
__device__ float g_t  [MAX_E * 128];
__device__ float g_e  [MAX_E * 128];

__device__ __forceinline__ float silu_f(float x) {
    return x / (1.0f + __expf(-x));
}

// ---------------------------------------------------------------------------
// Generic fused GEMM: C[m][n] = (res? res[m][n] : 0) + silu(sum_k A[m][k]*W[n][k] + bias[n])
// W is [Nout, K] row-major (PyTorch/JAX dense weight layout, x @ W^T).
// BM=BN=128, BK=8, 8x8 microtile, 256 threads. K % 8 == 0, Nout % 128 == 0.
// ---------------------------------------------------------------------------
__global__ void __launch_bounds__(256, 2) gemm_kernel(
    const float* __restrict__ A, const float* __restrict__ W,
    const float* __restrict__ bias, float* __restrict__ C,
    const float* __restrict__ res, int M, int N, int K)
{
    __shared__ float As[8][128];
    __shared__ float Bs[8][128];

    const int tid = threadIdx.x;
    const int br  = blockIdx.x * 128;
    const int bc  = blockIdx.y * 128;
    const int tr  = (tid >> 4) * 8;
    const int tc  = (tid & 15) * 8;
    const int lr  = tid >> 1;          // 0..127
    const int kq  = (tid & 1) * 4;     // 0 or 4

    float acc[8][8];
#pragma unroll
    for (int i = 0; i < 8; i++)
#pragma unroll
        for (int j = 0; j < 8; j++) acc[i][j] = 0.f;

    const int  arow = br + lr;
    const bool a_ok = arow < M;
    const float* Aptr = A + (size_t)arow * K + kq;
    const float* Wptr = W + (size_t)(bc + lr) * K + kq;

    for (int k0 = 0; k0 < K; k0 += 8) {
        float4 av = a_ok ? *(const float4*)(Aptr + k0) : make_float4(0.f, 0.f, 0.f, 0.f);
        float4 wv = *(const float4*)(Wptr + k0);
        As[kq + 0][lr] = av.x; As[kq + 1][lr] = av.y;
        As[kq + 2][lr] = av.z; As[kq + 3][lr] = av.w;
        Bs[kq + 0][lr] = wv.x; Bs[kq + 1][lr] = wv.y;
        Bs[kq + 2][lr] = wv.z; Bs[kq + 3][lr] = wv.w;
        __syncthreads();
#pragma unroll
        for (int k = 0; k < 8; k++) {
            float a[8], b[8];
#pragma unroll
            for (int i = 0; i < 8; i++) a[i] = As[k][tr + i];
#pragma unroll
            for (int j = 0; j < 8; j++) b[j] = Bs[k][tc + j];
#pragma unroll
            for (int i = 0; i < 8; i++)
#pragma unroll
                for (int j = 0; j < 8; j++)
                    acc[i][j] = fmaf(a[i], b[j], acc[i][j]);
        }
        __syncthreads();
    }

    float bb[8];
#pragma unroll
    for (int j = 0; j < 8; j++) bb[j] = bias[bc + tc + j];

#pragma unroll
    for (int i = 0; i < 8; i++) {
        int r = br + tr + i;
        if (r < M) {
            float* crow = C + (size_t)r * N + bc + tc;
            if (res) {
                const float* rrow = res + (size_t)r * N + bc + tc;
#pragma unroll
                for (int j = 0; j < 8; j++)
                    crow[j] = rrow[j] + silu_f(acc[i][j] + bb[j]);
            } else {
#pragma unroll
                for (int j = 0; j < 8; j++)
                    crow[j] = silu_f(acc[i][j] + bb[j]);
            }
        }
    }
}

// ---------------------------------------------------------------------------
// Message kernel (per layer): e_l = silu(e @ geom_w^T + geom_b);
// msg = e_l * hd[src]; atomicAdd into agg[dst]. 128 edges per block, F=K=128.
// ---------------------------------------------------------------------------
__global__ void __launch_bounds__(256, 2) message_kernel(
    const float* __restrict__ e, const float* __restrict__ gw,
    const float* __restrict__ gb, const float* __restrict__ hd,
    const int* __restrict__ ei, float* __restrict__ agg, int E)
{
    __shared__ float As[8][128];
    __shared__ float Bs[8][128];
    __shared__ int s_src[128];
    __shared__ int s_dst[128];

    const int tid = threadIdx.x;
    const int br  = blockIdx.x * 128;

    if (tid < 128) {
        int ge = br + tid;
        s_src[tid] = (ge < E) ? ei[ge]     : 0;
        s_dst[tid] = (ge < E) ? ei[E + ge] : 0;
    }

    const int tr = (tid >> 4) * 8;
    const int tc = (tid & 15) * 8;
    const int lr = tid >> 1;
    const int kq = (tid & 1) * 4;

    float acc[8][8];
#pragma unroll
    for (int i = 0; i < 8; i++)
#pragma unroll
        for (int j = 0; j < 8; j++) acc[i][j] = 0.f;

    const int  arow = br + lr;
    const bool a_ok = arow < E;
    const float* Aptr = e  + (size_t)arow * 128 + kq;
    const float* Wptr = gw + (size_t)lr   * 128 + kq;

    for (int k0 = 0; k0 < 128; k0 += 8) {
        float4 av = a_ok ? *(const float4*)(Aptr + k0) : make_float4(0.f, 0.f, 0.f, 0.f);
        float4 wv = *(const float4*)(Wptr + k0);
        As[kq + 0][lr] = av.x; As[kq + 1][lr] = av.y;
        As[kq + 2][lr] = av.z; As[kq + 3][lr] = av.w;
        Bs[kq + 0][lr] = wv.x; Bs[kq + 1][lr] = wv.y;
        Bs[kq + 2][lr] = wv.z; Bs[kq + 3][lr] = wv.w;
        __syncthreads();
#pragma unroll
        for (int k = 0; k < 8; k++) {
            float a[8], b[8];
#pragma unroll
            for (int i = 0; i < 8; i++) a[i] = As[k][tr + i];
#pragma unroll
            for (int j = 0; j < 8; j++) b[j] = Bs[k][tc + j];
#pragma unroll
            for (int i = 0; i < 8; i++)
#pragma unroll
                for (int j = 0; j < 8; j++)
                    acc[i][j] = fmaf(a[i], b[j], acc[i][j]);
        }
        __syncthreads();
    }

    float bb[8];
#pragma unroll
    for (int j = 0; j < 8; j++) bb[j] = gb[tc + j];

#pragma unroll
    for (int i = 0; i < 8; i++) {
        int r  = tr + i;
        int ge = br + r;
        if (ge < E) {
            int s = s_src[r];
            int d = s_dst[r];
            float4 h0 = *(const float4*)(hd + (size_t)s * 128 + tc);
            float4 h1 = *(const float4*)(hd + (size_t)s * 128 + tc + 4);
            float hv[8] = {h0.x, h0.y, h0.z, h0.w, h1.x, h1.y, h1.z, h1.w};
            float* ap = agg + (size_t)d * 128 + tc;
#pragma unroll
            for (int j = 0; j < 8; j++)
                atomicAdd(ap + j, silu_f(acc[i][j] + bb[j]) * hv[j]);
        }
    }
}

// ---------------------------------------------------------------------------
// Edge stage 1: t = silu([rel_pos @ W1^T ; edge_attr @ W12^T] + [b1;b12])
// 128 edges per block, 64+64 output cols.
// ---------------------------------------------------------------------------
__global__ void __launch_bounds__(256) edge_stage1(
    const float* __restrict__ rel_pos, const float* __restrict__ edge_attr,
    const float* __restrict__ w1, const float* __restrict__ b1,
    const float* __restrict__ w12, const float* __restrict__ b12,
    float* __restrict__ t, int E)
{
    __shared__ float rp_s[128][3];
    __shared__ float ea_s[128][53];
    __shared__ float w1_s[64][3];
    __shared__ float w12_s[64][53];
    __shared__ float b_s[128];

    const int tid = threadIdx.x;
    const int br  = blockIdx.x * 128;

    for (int i = tid; i < 64 * 3; i += 256)  w1_s[i / 3][i % 3]   = w1[i];
    for (int i = tid; i < 64 * 50; i += 256) w12_s[i / 50][i % 50] = w12[i];
    if (tid < 64)              b_s[tid] = b1[tid];
    else if (tid < 128)        b_s[tid] = b12[tid - 64];
    for (int i = tid; i < 128 * 3; i += 256) {
        int r = i / 3, k = i % 3, ge = br + r;
        rp_s[r][k] = (ge < E) ? rel_pos[(size_t)ge * 3 + k] : 0.f;
    }
    for (int i = tid; i < 128 * 50; i += 256) {
        int r = i / 50, k = i % 50, ge = br + r;
        ea_s[r][k] = (ge < E) ? edge_attr[(size_t)ge * 50 + k] : 0.f;
    }
    __syncthreads();

    const int tr = (tid >> 4) * 8;
    const int tc = (tid & 15) * 8;
    float acc[8][8];
#pragma unroll
    for (int i = 0; i < 8; i++)
#pragma unroll
        for (int j = 0; j < 8; j++) acc[i][j] = 0.f;

    if (tc < 64) {
#pragma unroll
        for (int k = 0; k < 3; k++) {
            float a[8], w[8];
#pragma unroll
            for (int i = 0; i < 8; i++) a[i] = rp_s[tr + i][k];
#pragma unroll
            for (int j = 0; j < 8; j++) w[j] = w1_s[tc + j][k];
#pragma unroll
            for (int i = 0; i < 8; i++)
#pragma unroll
                for (int j = 0; j < 8; j++)
                    acc[i][j] = fmaf(a[i], w[j], acc[i][j]);
        }
    } else {
        const int c0 = tc - 64;
        for (int k = 0; k < 50; k++) {
            float a[8], w[8];
#pragma unroll
            for (int i = 0; i < 8; i++) a[i] = ea_s[tr + i][k];
#pragma unroll
            for (int j = 0; j < 8; j++) w[j] = w12_s[c0 + j][k];
#pragma unroll
            for (int i = 0; i < 8; i++)
#pragma unroll
                for (int j = 0; j < 8; j++)
                    acc[i][j] = fmaf(a[i], w[j], acc[i][j]);
        }
    }

#pragma unroll
    for (int i = 0; i < 8; i++) {
        int ge = br + tr + i;
        if (ge < E) {
            float* row = t + (size_t)ge * 128 + tc;
#pragma unroll
            for (int j = 0; j < 8; j++)
                row[j] = silu_f(acc[i][j] + b_s[tc + j]);
        }
    }
}

// ---------------------------------------------------------------------------
// Node embedding concat: h0 = [emb_w[z] (224) ; tag_emb_w[tag] (32)]
// ---------------------------------------------------------------------------
__global__ void embed_concat(const int* __restrict__ z, const int* __restrict__ tag,
                             const float* __restrict__ emb_w,
                             const float* __restrict__ tag_emb_w,
                             float* __restrict__ h0, int N)
{
    int idx = blockIdx.x * blockDim.x + threadIdx.x;   // over N*64 float4
    if (idx >= N * 64) return;
    int n = idx >> 6, c4 = idx & 63;
    float4 v;
    if (c4 < 56) v = ((const float4*)(emb_w + (size_t)z[n] * 224))[c4];
    else         v = ((const float4*)(tag_emb_w + (size_t)tag[n] * 32))[c4 - 56];
    ((float4*)(h0 + (size_t)n * 256))[c4] = v;
}

// ---------------------------------------------------------------------------
// GraphNorm stats: per-column sum and sum of squares over N rows.
// ---------------------------------------------------------------------------
__global__ void stats_kernel(const float* __restrict__ agg, float* __restrict__ stats, int N)
{
    int col = threadIdx.x;                     // 128 threads
    float s = 0.f, s2 = 0.f;
    for (int r = blockIdx.x; r < N; r += gridDim.x) {
        float v = agg[(size_t)r * 128 + col];
        s += v;
        s2 = fmaf(v, v, s2);
    }
    atomicAdd(&stats[col], s);
    atomicAdd(&stats[128 + col], s2);
}

__global__ void finalize_stats(float* stats, const float* __restrict__ gnw,
                               const float* __restrict__ gnms, int N)
{
    int f = threadIdx.x;
    float inv  = 1.f / (float)N;
    float mean = stats[f] * inv;
    float m2   = stats[128 + f] * inv;
    float ms   = gnms[f];
    // var = E[(a - mean*ms)^2] = m2 - 2*ms*mean^2 + ms^2*mean^2
    float var = m2 - ms * (2.f - ms) * mean * mean;
    stats[256 + f] = mean * ms;
    stats[384 + f] = gnw[f] * rsqrtf(var + 1e-5f);
}

__global__ void apply_gn(const float* __restrict__ agg, const float* __restrict__ stats,
                         const float* __restrict__ gnb, float* __restrict__ x, int total)
{
    int i = blockIdx.x * blockDim.x + threadIdx.x;
    if (i >= total) return;
    int f = i & 127;
    float v = stats[384 + f] * (agg[i] - stats[256 + f]) + gnb[f];
    x[i] = silu_f(v);
}

// ---------------------------------------------------------------------------
// Output: warp per node: dot(h1[n], out2_w) + b, segment-add into out[batch[n]]
// ---------------------------------------------------------------------------
__global__ void out_reduce(const float* __restrict__ h1, const float* __restrict__ w2,
                           const float* __restrict__ b2, const int* __restrict__ batch,
                           float* __restrict__ out, int N)
{
    int gw   = (blockIdx.x * blockDim.x + threadIdx.x) >> 5;
    int lane = threadIdx.x & 31;
    if (gw >= N) return;
    float4 a = ((const float4*)(h1 + (size_t)gw * 128))[lane];
    float4 b = ((const float4*)w2)[lane];
    float s = a.x * b.x + a.y * b.y + a.z * b.z + a.w * b.w;
#pragma unroll
    for (int o = 16; o > 0; o >>= 1) s += __shfl_xor_sync(0xffffffffu, s, o);
    if (lane == 0) atomicAdd(&out[batch[gw]], s + b2[0]);
}

__global__ void zero_kernel(float* __restrict__ p, int n4)
{
    int i = blockIdx.x * blockDim.x + threadIdx.x;
    if (i < n4) ((float4*)p)[i] = make_float4(0.f, 0.f, 0.f, 0.f);
}

// ---------------------------------------------------------------------------
// Launch
// ---------------------------------------------------------------------------
extern "C" void kernel_launch(void* const* d_in, const int* in_sizes, int n_in,
                              void* d_out, int out_size)
{
    const int*   z         = (const int*)  d_in[0];
    const int*   tag       = (const int*)  d_in[1];
    const float* rel_pos   = (const float*)d_in[2];
    const float* edge_attr = (const float*)d_in[3];
    const int*   ei        = (const int*)  d_in[4];
    const int*   batch     = (const int*)  d_in[5];
    const float* lin_e1_w  = (const float*)d_in[6];
    const float* lin_e1_b  = (const float*)d_in[7];
    const float* lin_e12_w = (const float*)d_in[8];
    const float* lin_e12_b = (const float*)d_in[9];
    const float* lin_e2_w  = (const float*)d_in[10];
    const float* lin_e2_b  = (const float*)d_in[11];
    const float* emb_w     = (const float*)d_in[12];
    const float* tag_emb_w = (const float*)d_in[13];
    const float* lin_w     = (const float*)d_in[14];
    const float* lin_b     = (const float*)d_in[15];
    const float* lin2_w    = (const float*)d_in[16];
    const float* lin2_b    = (const float*)d_in[17];
    const float* geom_w    = (const float*)d_in[18];
    const float* geom_b    = (const float*)d_in[19];
    const float* down_w    = (const float*)d_in[20];
    const float* down_b    = (const float*)d_in[21];
    const float* up_w      = (const float*)d_in[22];
    const float* up_b      = (const float*)d_in[23];
    const float* gn_w      = (const float*)d_in[24];
    const float* gn_b      = (const float*)d_in[25];
    const float* gn_ms     = (const float*)d_in[26];
    const float* out1_w    = (const float*)d_in[27];
    const float* out1_b    = (const float*)d_in[28];
    const float* out2_w    = (const float*)d_in[29];
    const float* out2_b    = (const float*)d_in[30];
    float*       out       = (float*)d_out;

    const int N = in_sizes[0];
    const int E = in_sizes[2] / 3;

    float *h0, *hb, *h, *hd, *agg, *stats, *t, *e;
    cudaGetSymbolAddress((void**)&h0,    g_h0);
    cudaGetSymbolAddress((void**)&hb,    g_hb);
    cudaGetSymbolAddress((void**)&h,     g_h);
    cudaGetSymbolAddress((void**)&hd,    g_hd);
    cudaGetSymbolAddress((void**)&agg,   g_agg);
    cudaGetSymbolAddress((void**)&stats, g_stats);
    cudaGetSymbolAddress((void**)&t,     g_t);
    cudaGetSymbolAddress((void**)&e,     g_e);

    const int mbn = (N + 127) / 128;
    const int mbe = (E + 127) / 128;

    // Node embedding
    embed_concat<<<(N * 64 + 255) / 256, 256>>>(z, tag, emb_w, tag_emb_w, h0, N);
    gemm_kernel<<<dim3(mbn, 2), 256>>>(h0, lin_w,  lin_b,  hb, nullptr, N, 256, 256);
    gemm_kernel<<<dim3(mbn, 2), 256>>>(hb, lin2_w, lin2_b, h,  nullptr, N, 256, 256);

    // Edge embedding
    edge_stage1<<<mbe, 256>>>(rel_pos, edge_attr, lin_e1_w, lin_e1_b,
                              lin_e12_w, lin_e12_b, t, E);
    gemm_kernel<<<dim3(mbe, 1), 256>>>(t, lin_e2_w, lin_e2_b, e, nullptr, E, 128, 128);

    // Interaction layers
    for (int l = 0; l < 3; l++) {
        gemm_kernel<<<dim3(mbn, 1), 256>>>(h, down_w + (size_t)l * 128 * 256,
                                           down_b + l * 128, hd, nullptr, N, 128, 256);
        zero_kernel<<<(N * 32 + 255) / 256, 256>>>(agg, N * 32);   // N*128 floats = N*32 float4
        zero_kernel<<<1, 64>>>(stats, 64);                          // 256 floats
        message_kernel<<<mbe, 256>>>(e, geom_w + (size_t)l * 128 * 128,
                                     geom_b + l * 128, hd, ei, agg, E);
        stats_kernel<<<256, 128>>>(agg, stats, N);
        finalize_stats<<<1, 128>>>(stats, gn_w + l * 128, gn_ms + l * 128, N);
        apply_gn<<<(N * 128 + 255) / 256, 256>>>(agg, stats, gn_b + l * 128, hd, N * 128);
        gemm_kernel<<<dim3(mbn, 2), 256>>>(hd, up_w + (size_t)l * 256 * 128,
                                           up_b + l * 256, h, h, N, 256, 128);
    }

    // Output block
    gemm_kernel<<<dim3(mbn, 1), 256>>>(h, out1_w, out1_b, hd, nullptr, N, 128, 256);
    zero_kernel<<<1, 8>>>(out, 8);   // 32 floats
    out_reduce<<<(N * 32 + 255) / 256, 256>>>(hd, out2_w, out2_b, batch, out, N);
}

// round 4
// speedup vs baseline: 1.1738x; 1.1738x over previous
#include <cuda_runtime.h>

// ---------------------------------------------------------------------------
// FAENet forward, fp32. N=50000 nodes, E=800000 edges, H=256, F=128, G=50, L=3.
// ---------------------------------------------------------------------------

#define MAX_N 50000
#define MAX_E 800000

__device__ float g_h0 [MAX_N * 256];
__device__ float g_hb [MAX_N * 256];
__device__ float g_h  [MAX_N * 256];
__device__ float g_hd [MAX_N * 128];
__device__ float g_agg[MAX_N * 128];
__device__ float g_stats[512];
__device__ float g_t  [MAX_E * 128];
__device__ float g_e  [MAX_E * 128];

__device__ __forceinline__ float silu_f(float x) {
    return x / (1.0f + __expf(-x));
}

__device__ __forceinline__ void red_add_v4(float* p, float a, float b, float c, float d) {
    asm volatile("red.global.add.v4.f32 [%0], {%1,%2,%3,%4};"
                 :: "l"(p), "f"(a), "f"(b), "f"(c), "f"(d) : "memory");
}

// ---------------------------------------------------------------------------
// Fused GEMM: C = (res?) + silu(A @ W^T + bias). W is [Nout,K] row-major.
// BM=BN=128, BK=16, 8x8 microtile, 256 threads. Vectorized LDS.128 inner loop.
// K % 16 == 0, Nout % 128 == 0.
// ---------------------------------------------------------------------------
__global__ void __launch_bounds__(256, 2) gemm_kernel(
    const float* __restrict__ A, const float* __restrict__ W,
    const float* __restrict__ bias, float* __restrict__ C,
    const float* __restrict__ res, int M, int N, int K)
{
    __shared__ float As[16][128];
    __shared__ float Bs[16][128];

    const int tid = threadIdx.x;
    const int br  = blockIdx.x * 128;
    const int bc  = blockIdx.y * 128;
    const int tr  = (tid >> 4) * 8;
    const int tc  = (tid & 15) * 8;
    const int lr  = tid & 127;          // conflict-free STS: lane -> distinct bank
    const int kq  = (tid >> 7) * 8;     // 0 or 8

    float acc[8][8];
#pragma unroll
    for (int i = 0; i < 8; i++)
#pragma unroll
        for (int j = 0; j < 8; j++) acc[i][j] = 0.f;

    const int  arow = br + lr;
    const bool a_ok = arow < M;
    const float* Ap = A + (size_t)arow * K + kq;
    const float* Wp = W + (size_t)(bc + lr) * K + kq;

    for (int k0 = 0; k0 < K; k0 += 16) {
        float4 av0 = a_ok ? *(const float4*)(Ap + k0)     : make_float4(0.f,0.f,0.f,0.f);
        float4 av1 = a_ok ? *(const float4*)(Ap + k0 + 4) : make_float4(0.f,0.f,0.f,0.f);
        float4 wv0 = *(const float4*)(Wp + k0);
        float4 wv1 = *(const float4*)(Wp + k0 + 4);
        As[kq + 0][lr] = av0.x; As[kq + 1][lr] = av0.y;
        As[kq + 2][lr] = av0.z; As[kq + 3][lr] = av0.w;
        As[kq + 4][lr] = av1.x; As[kq + 5][lr] = av1.y;
        As[kq + 6][lr] = av1.z; As[kq + 7][lr] = av1.w;
        Bs[kq + 0][lr] = wv0.x; Bs[kq + 1][lr] = wv0.y;
        Bs[kq + 2][lr] = wv0.z; Bs[kq + 3][lr] = wv0.w;
        Bs[kq + 4][lr] = wv1.x; Bs[kq + 5][lr] = wv1.y;
        Bs[kq + 6][lr] = wv1.z; Bs[kq + 7][lr] = wv1.w;
        __syncthreads();
#pragma unroll
        for (int k = 0; k < 16; k++) {
            float4 a0 = *(const float4*)&As[k][tr];
            float4 a1 = *(const float4*)&As[k][tr + 4];
            float4 b0 = *(const float4*)&Bs[k][tc];
            float4 b1 = *(const float4*)&Bs[k][tc + 4];
            float a[8] = {a0.x, a0.y, a0.z, a0.w, a1.x, a1.y, a1.z, a1.w};
            float b[8] = {b0.x, b0.y, b0.z, b0.w, b1.x, b1.y, b1.z, b1.w};
#pragma unroll
            for (int i = 0; i < 8; i++)
#pragma unroll
                for (int j = 0; j < 8; j++)
                    acc[i][j] = fmaf(a[i], b[j], acc[i][j]);
        }
        __syncthreads();
    }

    float bb[8];
#pragma unroll
    for (int j = 0; j < 8; j++) bb[j] = bias[bc + tc + j];

#pragma unroll
    for (int i = 0; i < 8; i++) {
        int r = br + tr + i;
        if (r < M) {
            float* crow = C + (size_t)r * N + bc + tc;
            float v[8];
#pragma unroll
            for (int j = 0; j < 8; j++) v[j] = silu_f(acc[i][j] + bb[j]);
            if (res) {
                const float* rrow = res + (size_t)r * N + bc + tc;
                float4 r0 = *(const float4*)rrow;
                float4 r1 = *(const float4*)(rrow + 4);
                v[0] += r0.x; v[1] += r0.y; v[2] += r0.z; v[3] += r0.w;
                v[4] += r1.x; v[5] += r1.y; v[6] += r1.z; v[7] += r1.w;
            }
            *(float4*)crow       = make_float4(v[0], v[1], v[2], v[3]);
            *(float4*)(crow + 4) = make_float4(v[4], v[5], v[6], v[7]);
        }
    }
}

// ---------------------------------------------------------------------------
// Message kernel: e_l = silu(e @ geom_w^T + geom_b); msg = e_l * hd[src];
// red.v4 into agg[dst]. 128 edges/block, K=N=128.
// ---------------------------------------------------------------------------
__global__ void __launch_bounds__(256, 2) message_kernel(
    const float* __restrict__ e, const float* __restrict__ gw,
    const float* __restrict__ gb, const float* __restrict__ hd,
    const int* __restrict__ ei, float* __restrict__ agg, int E)
{
    __shared__ float As[16][128];
    __shared__ float Bs[16][128];
    __shared__ int s_src[128];
    __shared__ int s_dst[128];

    const int tid = threadIdx.x;
    const int br  = blockIdx.x * 128;

    if (tid < 128) {
        int ge = br + tid;
        s_src[tid] = (ge < E) ? ei[ge]     : 0;
        s_dst[tid] = (ge < E) ? ei[E + ge] : 0;
    }

    const int tr = (tid >> 4) * 8;
    const int tc = (tid & 15) * 8;
    const int lr = tid & 127;
    const int kq = (tid >> 7) * 8;

    float acc[8][8];
#pragma unroll
    for (int i = 0; i < 8; i++)
#pragma unroll
        for (int j = 0; j < 8; j++) acc[i][j] = 0.f;

    const int  arow = br + lr;
    const bool a_ok = arow < E;
    const float* Ap = e  + (size_t)arow * 128 + kq;
    const float* Wp = gw + (size_t)lr   * 128 + kq;

    for (int k0 = 0; k0 < 128; k0 += 16) {
        float4 av0 = a_ok ? *(const float4*)(Ap + k0)     : make_float4(0.f,0.f,0.f,0.f);
        float4 av1 = a_ok ? *(const float4*)(Ap + k0 + 4) : make_float4(0.f,0.f,0.f,0.f);
        float4 wv0 = *(const float4*)(Wp + k0);
        float4 wv1 = *(const float4*)(Wp + k0 + 4);
        As[kq + 0][lr] = av0.x; As[kq + 1][lr] = av0.y;
        As[kq + 2][lr] = av0.z; As[kq + 3][lr] = av0.w;
        As[kq + 4][lr] = av1.x; As[kq + 5][lr] = av1.y;
        As[kq + 6][lr] = av1.z; As[kq + 7][lr] = av1.w;
        Bs[kq + 0][lr] = wv0.x; Bs[kq + 1][lr] = wv0.y;
        Bs[kq + 2][lr] = wv0.z; Bs[kq + 3][lr] = wv0.w;
        Bs[kq + 4][lr] = wv1.x; Bs[kq + 5][lr] = wv1.y;
        Bs[kq + 6][lr] = wv1.z; Bs[kq + 7][lr] = wv1.w;
        __syncthreads();
#pragma unroll
        for (int k = 0; k < 16; k++) {
            float4 a0 = *(const float4*)&As[k][tr];
            float4 a1 = *(const float4*)&As[k][tr + 4];
            float4 b0 = *(const float4*)&Bs[k][tc];
            float4 b1 = *(const float4*)&Bs[k][tc + 4];
            float a[8] = {a0.x, a0.y, a0.z, a0.w, a1.x, a1.y, a1.z, a1.w};
            float b[8] = {b0.x, b0.y, b0.z, b0.w, b1.x, b1.y, b1.z, b1.w};
#pragma unroll
            for (int i = 0; i < 8; i++)
#pragma unroll
                for (int j = 0; j < 8; j++)
                    acc[i][j] = fmaf(a[i], b[j], acc[i][j]);
        }
        __syncthreads();
    }

    float bb[8];
#pragma unroll
    for (int j = 0; j < 8; j++) bb[j] = gb[tc + j];

#pragma unroll
    for (int i = 0; i < 8; i++) {
        int r  = tr + i;
        int ge = br + r;
        if (ge < E) {
            int s = s_src[r];
            int d = s_dst[r];
            float4 h0 = *(const float4*)(hd + (size_t)s * 128 + tc);
            float4 h1 = *(const float4*)(hd + (size_t)s * 128 + tc + 4);
            float* ap = agg + (size_t)d * 128 + tc;
            red_add_v4(ap,
                       silu_f(acc[i][0] + bb[0]) * h0.x,
                       silu_f(acc[i][1] + bb[1]) * h0.y,
                       silu_f(acc[i][2] + bb[2]) * h0.z,
                       silu_f(acc[i][3] + bb[3]) * h0.w);
            red_add_v4(ap + 4,
                       silu_f(acc[i][4] + bb[4]) * h1.x,
                       silu_f(acc[i][5] + bb[5]) * h1.y,
                       silu_f(acc[i][6] + bb[6]) * h1.z,
                       silu_f(acc[i][7] + bb[7]) * h1.w);
        }
    }
}

// ---------------------------------------------------------------------------
// Edge stage 1: t = silu([rel_pos | edge_attr] @ [W1|W12]^T + [b1;b12])
// Same GEMM structure, K padded to 56 (chunks of 8), on-the-fly concat.
// ---------------------------------------------------------------------------
__global__ void __launch_bounds__(256, 2) edge_stage1(
    const float* __restrict__ rel_pos, const float* __restrict__ edge_attr,
    const float* __restrict__ w1, const float* __restrict__ b1,
    const float* __restrict__ w12, const float* __restrict__ b12,
    float* __restrict__ t, int E)
{
    __shared__ float As[8][128];
    __shared__ float Bs[8][128];

    const int tid = threadIdx.x;
    const int br  = blockIdx.x * 128;
    const int tr  = (tid >> 4) * 8;
    const int tc  = (tid & 15) * 8;
    const int lr  = tid & 127;
    const int kq  = (tid >> 7) * 4;   // 0 or 4

    float acc[8][8];
#pragma unroll
    for (int i = 0; i < 8; i++)
#pragma unroll
        for (int j = 0; j < 8; j++) acc[i][j] = 0.f;

    const int  ge   = br + lr;
    const bool e_ok = ge < E;

    for (int k0 = 0; k0 < 56; k0 += 8) {
#pragma unroll
        for (int q = 0; q < 4; q++) {
            int k = k0 + kq + q;
            float av = 0.f, wv = 0.f;
            if (e_ok) {
                if (k < 3)       av = rel_pos[(size_t)ge * 3 + k];
                else if (k < 53) av = edge_attr[(size_t)ge * 50 + (k - 3)];
            }
            if (lr < 64) {
                if (k < 3)       wv = w1[lr * 3 + k];
            } else {
                if (k >= 3 && k < 53) wv = w12[(lr - 64) * 50 + (k - 3)];
            }
            As[kq + q][lr] = av;
            Bs[kq + q][lr] = wv;
        }
        __syncthreads();
#pragma unroll
        for (int k = 0; k < 8; k++) {
            float4 a0 = *(const float4*)&As[k][tr];
            float4 a1 = *(const float4*)&As[k][tr + 4];
            float4 b0 = *(const float4*)&Bs[k][tc];
            float4 b1 = *(const float4*)&Bs[k][tc + 4];
            float a[8] = {a0.x, a0.y, a0.z, a0.w, a1.x, a1.y, a1.z, a1.w};
            float b[8] = {b0.x, b0.y, b0.z, b0.w, b1.x, b1.y, b1.z, b1.w};
#pragma unroll
            for (int i = 0; i < 8; i++)
#pragma unroll
                for (int j = 0; j < 8; j++)
                    acc[i][j] = fmaf(a[i], b[j], acc[i][j]);
        }
        __syncthreads();
    }

    float bb[8];
#pragma unroll
    for (int j = 0; j < 8; j++) {
        int c = tc + j;
        bb[j] = (c < 64) ? b1[c] : b12[c - 64];
    }

#pragma unroll
    for (int i = 0; i < 8; i++) {
        int g = br + tr + i;
        if (g < E) {
            float* row = t + (size_t)g * 128 + tc;
            float v[8];
#pragma unroll
            for (int j = 0; j < 8; j++) v[j] = silu_f(acc[i][j] + bb[j]);
            *(float4*)row       = make_float4(v[0], v[1], v[2], v[3]);
            *(float4*)(row + 4) = make_float4(v[4], v[5], v[6], v[7]);
        }
    }
}

// ---------------------------------------------------------------------------
__global__ void embed_concat(const int* __restrict__ z, const int* __restrict__ tag,
                             const float* __restrict__ emb_w,
                             const float* __restrict__ tag_emb_w,
                             float* __restrict__ h0, int N)
{
    int idx = blockIdx.x * blockDim.x + threadIdx.x;
    if (idx >= N * 64) return;
    int n = idx >> 6, c4 = idx & 63;
    float4 v;
    if (c4 < 56) v = ((const float4*)(emb_w + (size_t)z[n] * 224))[c4];
    else         v = ((const float4*)(tag_emb_w + (size_t)tag[n] * 32))[c4 - 56];
    ((float4*)(h0 + (size_t)n * 256))[c4] = v;
}

__global__ void stats_kernel(const float* __restrict__ agg, float* __restrict__ stats, int N)
{
    int col = threadIdx.x;
    float s = 0.f, s2 = 0.f;
    for (int r = blockIdx.x; r < N; r += gridDim.x) {
        float v = agg[(size_t)r * 128 + col];
        s += v;
        s2 = fmaf(v, v, s2);
    }
    atomicAdd(&stats[col], s);
    atomicAdd(&stats[128 + col], s2);
}

__global__ void finalize_stats(float* stats, const float* __restrict__ gnw,
                               const float* __restrict__ gnms, int N)
{
    int f = threadIdx.x;
    float inv  = 1.f / (float)N;
    float mean = stats[f] * inv;
    float m2   = stats[128 + f] * inv;
    float ms   = gnms[f];
    float var = m2 - ms * (2.f - ms) * mean * mean;
    stats[256 + f] = mean * ms;
    stats[384 + f] = gnw[f] * rsqrtf(var + 1e-5f);
}

__global__ void apply_gn(const float* __restrict__ agg, const float* __restrict__ stats,
                         const float* __restrict__ gnb, float* __restrict__ x, int total4)
{
    int i = blockIdx.x * blockDim.x + threadIdx.x;   // over float4
    if (i >= total4) return;
    int f = (i & 31) * 4;
    float4 v = ((const float4*)agg)[i];
    float4 o;
    o.x = silu_f(stats[384 + f + 0] * (v.x - stats[256 + f + 0]) + gnb[f + 0]);
    o.y = silu_f(stats[384 + f + 1] * (v.y - stats[256 + f + 1]) + gnb[f + 1]);
    o.z = silu_f(stats[384 + f + 2] * (v.z - stats[256 + f + 2]) + gnb[f + 2]);
    o.w = silu_f(stats[384 + f + 3] * (v.w - stats[256 + f + 3]) + gnb[f + 3]);
    ((float4*)x)[i] = o;
}

__global__ void out_reduce(const float* __restrict__ h1, const float* __restrict__ w2,
                           const float* __restrict__ b2, const int* __restrict__ batch,
                           float* __restrict__ out, int N)
{
    int gw   = (blockIdx.x * blockDim.x + threadIdx.x) >> 5;
    int lane = threadIdx.x & 31;
    if (gw >= N) return;
    float4 a = ((const float4*)(h1 + (size_t)gw * 128))[lane];
    float4 b = ((const float4*)w2)[lane];
    float s = a.x * b.x + a.y * b.y + a.z * b.z + a.w * b.w;
#pragma unroll
    for (int o = 16; o > 0; o >>= 1) s += __shfl_xor_sync(0xffffffffu, s, o);
    if (lane == 0) atomicAdd(&out[batch[gw]], s + b2[0]);
}

__global__ void zero_kernel(float* __restrict__ p, int n4)
{
    int i = blockIdx.x * blockDim.x + threadIdx.x;
    if (i < n4) ((float4*)p)[i] = make_float4(0.f, 0.f, 0.f, 0.f);
}

// ---------------------------------------------------------------------------
extern "C" void kernel_launch(void* const* d_in, const int* in_sizes, int n_in,
                              void* d_out, int out_size)
{
    const int*   z         = (const int*)  d_in[0];
    const int*   tag       = (const int*)  d_in[1];
    const float* rel_pos   = (const float*)d_in[2];
    const float* edge_attr = (const float*)d_in[3];
    const int*   ei        = (const int*)  d_in[4];
    const int*   batch     = (const int*)  d_in[5];
    const float* lin_e1_w  = (const float*)d_in[6];
    const float* lin_e1_b  = (const float*)d_in[7];
    const float* lin_e12_w = (const float*)d_in[8];
    const float* lin_e12_b = (const float*)d_in[9];
    const float* lin_e2_w  = (const float*)d_in[10];
    const float* lin_e2_b  = (const float*)d_in[11];
    const float* emb_w     = (const float*)d_in[12];
    const float* tag_emb_w = (const float*)d_in[13];
    const float* lin_w     = (const float*)d_in[14];
    const float* lin_b     = (const float*)d_in[15];
    const float* lin2_w    = (const float*)d_in[16];
    const float* lin2_b    = (const float*)d_in[17];
    const float* geom_w    = (const float*)d_in[18];
    const float* geom_b    = (const float*)d_in[19];
    const float* down_w    = (const float*)d_in[20];
    const float* down_b    = (const float*)d_in[21];
    const float* up_w      = (const float*)d_in[22];
    const float* up_b      = (const float*)d_in[23];
    const float* gn_w      = (const float*)d_in[24];
    const float* gn_b      = (const float*)d_in[25];
    const float* gn_ms     = (const float*)d_in[26];
    const float* out1_w    = (const float*)d_in[27];
    const float* out1_b    = (const float*)d_in[28];
    const float* out2_w    = (const float*)d_in[29];
    const float* out2_b    = (const float*)d_in[30];
    float*       out       = (float*)d_out;

    const int N = in_sizes[0];
    const int E = in_sizes[2] / 3;

    float *h0, *hb, *h, *hd, *agg, *stats, *t, *e;
    cudaGetSymbolAddress((void**)&h0,    g_h0);
    cudaGetSymbolAddress((void**)&hb,    g_hb);
    cudaGetSymbolAddress((void**)&h,     g_h);
    cudaGetSymbolAddress((void**)&hd,    g_hd);
    cudaGetSymbolAddress((void**)&agg,   g_agg);
    cudaGetSymbolAddress((void**)&stats, g_stats);
    cudaGetSymbolAddress((void**)&t,     g_t);
    cudaGetSymbolAddress((void**)&e,     g_e);

    const int mbn = (N + 127) / 128;
    const int mbe = (E + 127) / 128;

    // Node embedding
    embed_concat<<<(N * 64 + 255) / 256, 256>>>(z, tag, emb_w, tag_emb_w, h0, N);
    gemm_kernel<<<dim3(mbn, 2), 256>>>(h0, lin_w,  lin_b,  hb, nullptr, N, 256, 256);
    gemm_kernel<<<dim3(mbn, 2), 256>>>(hb, lin2_w, lin2_b, h,  nullptr, N, 256, 256);

    // Edge embedding
    edge_stage1<<<mbe, 256>>>(rel_pos, edge_attr, lin_e1_w, lin_e1_b,
                              lin_e12_w, lin_e12_b, t, E);
    gemm_kernel<<<dim3(mbe, 1), 256>>>(t, lin_e2_w, lin_e2_b, e, nullptr, E, 128, 128);

    // Interaction layers
    for (int l = 0; l < 3; l++) {
        gemm_kernel<<<dim3(mbn, 1), 256>>>(h, down_w + (size_t)l * 128 * 256,
                                           down_b + l * 128, hd, nullptr, N, 128, 256);
        zero_kernel<<<(N * 32 + 255) / 256, 256>>>(agg, N * 32);
        zero_kernel<<<1, 64>>>(stats, 64);
        message_kernel<<<mbe, 256>>>(e, geom_w + (size_t)l * 128 * 128,
                                     geom_b + l * 128, hd, ei, agg, E);
        stats_kernel<<<256, 128>>>(agg, stats, N);
        finalize_stats<<<1, 128>>>(stats, gn_w + l * 128, gn_ms + l * 128, N);
        apply_gn<<<(N * 32 + 255) / 256, 256>>>(agg, stats, gn_b + l * 128, hd, N * 32);
        gemm_kernel<<<dim3(mbn, 2), 256>>>(hd, up_w + (size_t)l * 256 * 128,
                                           up_b + l * 256, h, h, N, 256, 128);
    }

    // Output block
    gemm_kernel<<<dim3(mbn, 1), 256>>>(h, out1_w, out1_b, hd, nullptr, N, 128, 256);
    zero_kernel<<<1, 8>>>(out, 8);
    out_reduce<<<(N * 32 + 255) / 256, 256>>>(hd, out2_w, out2_b, batch, out, N);
}